// round 5
// baseline (speedup 1.0000x reference)
#include <cuda_runtime.h>
#include <cstdint>

// SparseAdam via inverted index + single fused streaming pass.
//
// Inputs: 0 idx i32[N], 1 grad f32[N,128], 2 emb f32[V,128], 3 step f32[V],
//         4 mem f32[V,128], 5 pow f32[V,128]
// Output: new_emb[V,128] | new_step[V] | new_mem[V,128] | new_pow[V,128]
//
// 3 graph nodes: memset(barrier ctr) -> build_index (zero/hist/scan/scatter
// fused via software grid barrier, 296 blocks = 2/SM guaranteed resident) ->
// update (3.63 GB streaming floor, hybrid gather with cnt==1 fast path).

#define DD 128
#define MAXE (1 << 21)
#define SCAN_BS 256
#define SCAN_PT 16
#define SCAN_TILE (SCAN_BS * SCAN_PT)   // 4096
#define MAX_SCAN_BLOCKS 1024
#define IDX_GRID 296                     // 148 SMs x 2 CTAs, all resident

__device__ int  g_counts[MAXE];
__device__ int  g_offsets[MAXE];     // scatter cursor (starts = scan output)
__device__ int4 g_meta[MAXE];        // {start, cnt, first_rowid, pad}
__device__ int  g_rowids[MAXE];
__device__ unsigned long long g_desc[MAX_SCAN_BLOCKS];
__device__ unsigned g_barcnt;        // grid-barrier counter (memset to 0)

// Software grid barrier: all IDX_GRID blocks co-resident by construction.
static __device__ __forceinline__ void grid_bar(unsigned target) {
    __syncthreads();
    if (threadIdx.x == 0) {
        __threadfence();                       // cumulative: publish block's writes
        atomicAdd(&g_barcnt, 1u);
        while (atomicAdd(&g_barcnt, 0u) < target) { }
        __threadfence();                       // acquire side
    }
    __syncthreads();
}

// ---------------------------------------------------------------------------
// Fused index build: zero -> hist -> lookback scan -> scatter.
// ---------------------------------------------------------------------------
__global__ void __launch_bounds__(256, 2)
build_index_k(const int* __restrict__ idx, int N, int V, int nb) {
    const int t   = threadIdx.x;
    const int bid = blockIdx.x;
    const int gt  = bid * SCAN_BS + t;
    const int gstride = IDX_GRID * SCAN_BS;

    // ---- Phase 0: zero counts + scan descriptors ----
    for (int i = gt; i < V; i += gstride) g_counts[i] = 0;
    for (int i = gt; i < MAX_SCAN_BLOCKS; i += gstride) g_desc[i] = 0ULL;
    grid_bar(1 * IDX_GRID);

    // ---- Phase 1: histogram (int4 vectorized) ----
    {
        const int n4 = N >> 2;
        const int4* idx4 = (const int4*)idx;
        for (int i = gt; i < n4; i += gstride) {
            int4 v = __ldg(idx4 + i);
            atomicAdd(&g_counts[v.x], 1);
            atomicAdd(&g_counts[v.y], 1);
            atomicAdd(&g_counts[v.z], 1);
            atomicAdd(&g_counts[v.w], 1);
        }
        for (int i = (n4 << 2) + gt; i < N; i += gstride)
            atomicAdd(&g_counts[__ldg(idx + i)], 1);
    }
    grid_bar(2 * IDX_GRID);

    // ---- Phase 2: exclusive scan with decoupled lookback (blocks < nb) ----
    if (bid < nb) {
        const int lane = t & 31;
        const int wid  = t >> 5;
        const int base = bid * SCAN_TILE + t * SCAN_PT;

        int c[SCAN_PT], v[SCAN_PT];
        int s = 0;
        #pragma unroll
        for (int i = 0; i < SCAN_PT; i++) {
            c[i] = (base + i < V) ? __ldcg(&g_counts[base + i]) : 0;  // L2, not L1
            v[i] = s;
            s += c[i];
        }

        int incl = s;
        #pragma unroll
        for (int d = 1; d < 32; d <<= 1) {
            int u = __shfl_up_sync(0xffffffffu, incl, d);
            if (lane >= d) incl += u;
        }

        __shared__ int wsum[SCAN_BS / 32];
        __shared__ int woff[SCAN_BS / 32];
        __shared__ int sh_total, sh_prefix;
        if (lane == 31) wsum[wid] = incl;
        __syncthreads();
        if (t < SCAN_BS / 32) {
            int x = wsum[t];
            int ss = x;
            #pragma unroll
            for (int d = 1; d < SCAN_BS / 32; d <<= 1) {
                int u = __shfl_up_sync(0xffu, ss, d);
                if (t >= d) ss += u;
            }
            woff[t] = ss - x;
            if (t == (SCAN_BS / 32) - 1) sh_total = ss;
        }
        __syncthreads();
        const int total = sh_total;

        if (t == 0) {
            if (bid == 0) {
                atomicExch(&g_desc[0],
                           (2ULL << 62) | (unsigned long long)(unsigned)total);
                sh_prefix = 0;
            } else {
                atomicExch(&g_desc[bid],
                           (1ULL << 62) | (unsigned long long)(unsigned)total);
                int prefix = 0;
                int j = bid - 1;
                while (true) {
                    unsigned long long d;
                    do { d = atomicAdd(&g_desc[j], 0ULL); } while ((d >> 62) == 0ULL);
                    prefix += (int)(unsigned)(d & 0xffffffffULL);
                    if ((d >> 62) == 2ULL) break;
                    j--;
                }
                atomicExch(&g_desc[bid],
                           (2ULL << 62) | (unsigned long long)(unsigned)(total + prefix));
                sh_prefix = prefix;
            }
        }
        __syncthreads();

        const int excl_thread = sh_prefix + woff[wid] + (incl - s);
        #pragma unroll
        for (int i = 0; i < SCAN_PT; i++) {
            if (base + i < V) {
                int start = excl_thread + v[i];
                g_offsets[base + i] = start;
                g_meta[base + i] = make_int4(start, c[i], 0, 0);
            }
        }
    }
    grid_bar(3 * IDX_GRID);

    // ---- Phase 3: scatter rowids; stash one rowid in meta.z (unique writer
    //      when cnt==1; racy-but-unused otherwise) ----
    {
        const int n4 = N >> 2;
        const int4* idx4 = (const int4*)idx;
        for (int i = gt; i < n4; i += gstride) {
            int4 v = __ldg(idx4 + i);
            int b = i << 2;
            g_rowids[atomicAdd(&g_offsets[v.x], 1)] = b;     g_meta[v.x].z = b;
            g_rowids[atomicAdd(&g_offsets[v.y], 1)] = b + 1; g_meta[v.y].z = b + 1;
            g_rowids[atomicAdd(&g_offsets[v.z], 1)] = b + 2; g_meta[v.z].z = b + 2;
            g_rowids[atomicAdd(&g_offsets[v.w], 1)] = b + 3; g_meta[v.w].z = b + 3;
        }
        for (int i = (n4 << 2) + gt; i < N; i += gstride) {
            int v = __ldg(idx + i);
            g_rowids[atomicAdd(&g_offsets[v], 1)] = i;
            g_meta[v].z = i;
        }
    }
}

// ---------------------------------------------------------------------------
// Fused gather + Adam update. One warp per vocab row, float4 per lane.
// cnt==1 fast path: meta carries the rowid, so chain is meta -> grad.
// cnt>=2: warp-uniform 4/2/1 batches, no duplicate loads.
// ---------------------------------------------------------------------------
__global__ void __launch_bounds__(256, 6)
sadam_update_k(const float4* __restrict__ grad,
               const float4* __restrict__ emb,
               const float*  __restrict__ step_in,
               const float4* __restrict__ mem,
               const float4* __restrict__ pw,
               float4* __restrict__ out_emb,
               float*  __restrict__ out_step,
               float4* __restrict__ out_mem,
               float4* __restrict__ out_pow,
               int V) {
    const long gtid = (long)blockIdx.x * blockDim.x + threadIdx.x;
    const long row  = gtid >> 5;
    if (row >= V) return;
    const int  lane = (int)(gtid & 31);
    const long i4   = row * (DD / 4) + lane;

    const int4  meta = __ldg(&g_meta[row]);     // {start, cnt, first, -}
    const float st   = __ldg(step_in + row);
    const int   cnt  = meta.y;

    float4 e = __ldcs(emb + i4);
    float4 m = __ldcs(mem + i4);
    float4 p = __ldcs(pw  + i4);

    float4 ne, nm, np;
    float  nstep;

    if (cnt > 0) {
        float4 gs;
        if (cnt == 1) {
            gs = __ldcs(grad + (long)meta.z * (DD / 4) + lane);
        } else {
            const int start = meta.x;
            gs = make_float4(0.f, 0.f, 0.f, 0.f);
            int j = 0;
            for (; j + 4 <= cnt; j += 4) {
                int r0 = __ldg(&g_rowids[start + j]);
                int r1 = __ldg(&g_rowids[start + j + 1]);
                int r2 = __ldg(&g_rowids[start + j + 2]);
                int r3 = __ldg(&g_rowids[start + j + 3]);
                float4 g0 = __ldcs(grad + (long)r0 * (DD / 4) + lane);
                float4 g1 = __ldcs(grad + (long)r1 * (DD / 4) + lane);
                float4 g2 = __ldcs(grad + (long)r2 * (DD / 4) + lane);
                float4 g3 = __ldcs(grad + (long)r3 * (DD / 4) + lane);
                gs.x += (g0.x + g1.x) + (g2.x + g3.x);
                gs.y += (g0.y + g1.y) + (g2.y + g3.y);
                gs.z += (g0.z + g1.z) + (g2.z + g3.z);
                gs.w += (g0.w + g1.w) + (g2.w + g3.w);
            }
            if (cnt - j >= 2) {
                int r0 = __ldg(&g_rowids[start + j]);
                int r1 = __ldg(&g_rowids[start + j + 1]);
                float4 g0 = __ldcs(grad + (long)r0 * (DD / 4) + lane);
                float4 g1 = __ldcs(grad + (long)r1 * (DD / 4) + lane);
                gs.x += g0.x + g1.x; gs.y += g0.y + g1.y;
                gs.z += g0.z + g1.z; gs.w += g0.w + g1.w;
                j += 2;
            }
            if (cnt - j) {
                int r0 = __ldg(&g_rowids[start + j]);
                float4 g0 = __ldcs(grad + (long)r0 * (DD / 4) + lane);
                gs.x += g0.x; gs.y += g0.y; gs.z += g0.z; gs.w += g0.w;
            }
        }
        nstep = st + 1.f;
        const float inv = 1.f / (float)cnt;
        const float d1 = 1.f - exp2f(nstep * -0.15200309344504997f);   // 1-0.9^s
        const float d2 = 1.f - exp2f(nstep * -0.0014434169010128458f); // 1-0.999^s
        const float c1  = 0.001f / d1;
        const float id2 = 1.f / d2;

        #define ADAM1(GS, M, P, E, NM, NP, NE)                       \
        {                                                             \
            float g = (GS) * inv;                                     \
            NM = 0.9f * (M) + 0.1f * g;                               \
            NP = 0.999f * (P) + 0.001f * (g * g);                     \
            float stdv = c1 * NM / (sqrtf(NP * id2) + 1e-8f);         \
            NE = (E) - stdv;                                          \
        }
        ADAM1(gs.x, m.x, p.x, e.x, nm.x, np.x, ne.x)
        ADAM1(gs.y, m.y, p.y, e.y, nm.y, np.y, ne.y)
        ADAM1(gs.z, m.z, p.z, e.z, nm.z, np.z, ne.z)
        ADAM1(gs.w, m.w, p.w, e.w, nm.w, np.w, ne.w)
        #undef ADAM1
    } else {
        nstep = st;
        ne = e; nm = m; np = p;
    }

    __stcs(out_emb + i4, ne);
    __stcs(out_mem + i4, nm);
    __stcs(out_pow + i4, np);
    if (lane == 0) out_step[row] = nstep;
}

// ---------------------------------------------------------------------------
extern "C" void kernel_launch(void* const* d_in, const int* in_sizes, int n_in,
                              void* d_out, int out_size) {
    const int*   idx  = (const int*)  d_in[0];
    const float* grad = (const float*)d_in[1];
    const float* emb  = (const float*)d_in[2];
    const float* step = (const float*)d_in[3];
    const float* mem  = (const float*)d_in[4];
    const float* pw   = (const float*)d_in[5];

    const int N = in_sizes[0];
    const int V = in_sizes[3];

    float* out      = (float*)d_out;
    float* out_emb  = out;
    float* out_step = out_emb + (long)V * DD;
    float* out_mem  = out_step + V;
    float* out_pow  = out_mem + (long)V * DD;

    // Reset the grid-barrier counter (everything else zeroed in-kernel).
    void* bar_ptr = nullptr;
    cudaGetSymbolAddress(&bar_ptr, g_barcnt);
    cudaMemsetAsync(bar_ptr, 0, sizeof(unsigned));

    const int nb = (V + SCAN_TILE - 1) / SCAN_TILE;
    build_index_k<<<IDX_GRID, SCAN_BS>>>(idx, N, V, nb);

    {
        const long threads = (long)V * 32;
        const int  blocks  = (int)((threads + 255) / 256);
        sadam_update_k<<<blocks, 256>>>((const float4*)grad, (const float4*)emb,
                                        step, (const float4*)mem, (const float4*)pw,
                                        (float4*)out_emb, out_step,
                                        (float4*)out_mem, (float4*)out_pow, V);
    }
}

// round 6
// speedup vs baseline: 1.0886x; 1.0886x over previous
#include <cuda_runtime.h>
#include <cstdint>

// SparseAdam via inverted index (counting sort) + single fused streaming pass.
//
// Inputs: 0 idx i32[N], 1 grad f32[N,128], 2 emb f32[V,128], 3 step f32[V],
//         4 mem f32[V,128], 5 pow f32[V,128]
// Output: new_emb[V,128] | new_step[V] | new_mem[V,128] | new_pow[V,128]
//
// Pipeline: memset -> hist -> lookback-scan (writes {start,cnt}) ->
//           scatter_ids -> update (3.63 GB streaming floor).
// Update gather is cnt-specialized (1 / 2 / loop) for MLP without dup loads.

#define DD 128
#define MAXE (1 << 21)
#define SCAN_BS 256
#define SCAN_PT 16
#define SCAN_TILE (SCAN_BS * SCAN_PT)   // 4096
#define MAX_SCAN_BLOCKS 1024

__device__ int  g_counts[MAXE];
__device__ int  g_offsets[MAXE];     // scatter cursor
__device__ int2 g_meta[MAXE];        // {start, cnt}
__device__ int  g_rowids[MAXE];
__device__ unsigned long long g_desc[MAX_SCAN_BLOCKS];

// ---------------------------------------------------------------------------
__global__ void hist_k(const int* __restrict__ idx, int N) {
    const int n4 = N >> 2;
    const int stride = gridDim.x * blockDim.x;
    const int4* idx4 = (const int4*)idx;
    for (int i = blockIdx.x * blockDim.x + threadIdx.x; i < n4; i += stride) {
        int4 v = __ldg(idx4 + i);
        atomicAdd(&g_counts[v.x], 1);
        atomicAdd(&g_counts[v.y], 1);
        atomicAdd(&g_counts[v.z], 1);
        atomicAdd(&g_counts[v.w], 1);
    }
    for (int i = (n4 << 2) + blockIdx.x * blockDim.x + threadIdx.x; i < N; i += stride)
        atomicAdd(&g_counts[__ldg(idx + i)], 1);
}

// ---------------------------------------------------------------------------
// Single-pass exclusive scan (decoupled lookback). counts -> offsets + meta.
// ---------------------------------------------------------------------------
__global__ void scan_lb_k(int V) {
    const int bid = blockIdx.x;
    const int t = threadIdx.x;
    const int lane = t & 31;
    const int wid = t >> 5;
    const int base = bid * SCAN_TILE + t * SCAN_PT;

    int c[SCAN_PT], v[SCAN_PT];
    int s = 0;
    #pragma unroll
    for (int i = 0; i < SCAN_PT; i++) {
        c[i] = (base + i < V) ? g_counts[base + i] : 0;
        v[i] = s;
        s += c[i];
    }

    int incl = s;
    #pragma unroll
    for (int d = 1; d < 32; d <<= 1) {
        int u = __shfl_up_sync(0xffffffffu, incl, d);
        if (lane >= d) incl += u;
    }

    __shared__ int wsum[SCAN_BS / 32];
    __shared__ int woff[SCAN_BS / 32];
    __shared__ int sh_total, sh_prefix;
    if (lane == 31) wsum[wid] = incl;
    __syncthreads();
    if (t < SCAN_BS / 32) {
        int x = wsum[t];
        int ss = x;
        #pragma unroll
        for (int d = 1; d < SCAN_BS / 32; d <<= 1) {
            int u = __shfl_up_sync(0xffu, ss, d);
            if (t >= d) ss += u;
        }
        woff[t] = ss - x;
        if (t == (SCAN_BS / 32) - 1) sh_total = ss;
    }
    __syncthreads();
    const int total = sh_total;

    if (t == 0) {
        if (bid == 0) {
            atomicExch(&g_desc[0],
                       (2ULL << 62) | (unsigned long long)(unsigned)total);
            sh_prefix = 0;
        } else {
            atomicExch(&g_desc[bid],
                       (1ULL << 62) | (unsigned long long)(unsigned)total);
            int prefix = 0;
            int j = bid - 1;
            while (true) {
                unsigned long long d;
                do { d = atomicAdd(&g_desc[j], 0ULL); } while ((d >> 62) == 0ULL);
                prefix += (int)(unsigned)(d & 0xffffffffULL);
                if ((d >> 62) == 2ULL) break;
                j--;
            }
            atomicExch(&g_desc[bid],
                       (2ULL << 62) | (unsigned long long)(unsigned)(total + prefix));
            sh_prefix = prefix;
        }
    }
    __syncthreads();

    const int excl_thread = sh_prefix + woff[wid] + (incl - s);
    #pragma unroll
    for (int i = 0; i < SCAN_PT; i++) {
        if (base + i < V) {
            int start = excl_thread + v[i];
            g_offsets[base + i] = start;
            g_meta[base + i] = make_int2(start, c[i]);
        }
    }
}

// ---------------------------------------------------------------------------
__global__ void scatter_ids_k(const int* __restrict__ idx, int N) {
    const int n4 = N >> 2;
    const int stride = gridDim.x * blockDim.x;
    const int4* idx4 = (const int4*)idx;
    for (int i = blockIdx.x * blockDim.x + threadIdx.x; i < n4; i += stride) {
        int4 v = __ldg(idx4 + i);
        int b = i << 2;
        g_rowids[atomicAdd(&g_offsets[v.x], 1)] = b;
        g_rowids[atomicAdd(&g_offsets[v.y], 1)] = b + 1;
        g_rowids[atomicAdd(&g_offsets[v.z], 1)] = b + 2;
        g_rowids[atomicAdd(&g_offsets[v.w], 1)] = b + 3;
    }
    for (int i = (n4 << 2) + blockIdx.x * blockDim.x + threadIdx.x; i < N; i += stride)
        g_rowids[atomicAdd(&g_offsets[__ldg(idx + i)], 1)] = i;
}

// ---------------------------------------------------------------------------
// Fused gather + Adam update. One warp per vocab row, float4 per lane.
// Gather: warp-uniform cnt specialization — cnt==1 (1 load), cnt==2 (2 loads
// issued in parallel), cnt>=3 (2-wide loop). No duplicate loads.
// ---------------------------------------------------------------------------
__global__ void __launch_bounds__(256, 6)
sadam_update_k(const float4* __restrict__ grad,
               const float4* __restrict__ emb,
               const float*  __restrict__ step_in,
               const float4* __restrict__ mem,
               const float4* __restrict__ pw,
               float4* __restrict__ out_emb,
               float*  __restrict__ out_step,
               float4* __restrict__ out_mem,
               float4* __restrict__ out_pow,
               int V) {
    const long gtid = (long)blockIdx.x * blockDim.x + threadIdx.x;
    const long row  = gtid >> 5;
    if (row >= V) return;
    const int  lane = (int)(gtid & 31);
    const long i4   = row * (DD / 4) + lane;

    const int2  meta = __ldg(&g_meta[row]);     // {start, cnt}
    const float st   = __ldg(step_in + row);
    const int   cnt  = meta.y;

    float4 e = __ldcs(emb + i4);
    float4 m = __ldcs(mem + i4);
    float4 p = __ldcs(pw  + i4);

    float4 ne, nm, np;
    float  nstep;

    if (cnt > 0) {
        const int start = meta.x;
        float4 gs;
        if (cnt == 1) {
            const int r0 = __ldg(&g_rowids[start]);
            gs = __ldcs(grad + (long)r0 * (DD / 4) + lane);
        } else if (cnt == 2) {
            const int r0 = __ldg(&g_rowids[start]);
            const int r1 = __ldg(&g_rowids[start + 1]);
            float4 g0 = __ldcs(grad + (long)r0 * (DD / 4) + lane);
            float4 g1 = __ldcs(grad + (long)r1 * (DD / 4) + lane);
            gs.x = g0.x + g1.x; gs.y = g0.y + g1.y;
            gs.z = g0.z + g1.z; gs.w = g0.w + g1.w;
        } else {
            gs = make_float4(0.f, 0.f, 0.f, 0.f);
            int j = 0;
            for (; j + 2 <= cnt; j += 2) {
                const int r0 = __ldg(&g_rowids[start + j]);
                const int r1 = __ldg(&g_rowids[start + j + 1]);
                float4 g0 = __ldcs(grad + (long)r0 * (DD / 4) + lane);
                float4 g1 = __ldcs(grad + (long)r1 * (DD / 4) + lane);
                gs.x += g0.x + g1.x; gs.y += g0.y + g1.y;
                gs.z += g0.z + g1.z; gs.w += g0.w + g1.w;
            }
            if (j < cnt) {
                const int r0 = __ldg(&g_rowids[start + j]);
                float4 g0 = __ldcs(grad + (long)r0 * (DD / 4) + lane);
                gs.x += g0.x; gs.y += g0.y; gs.z += g0.z; gs.w += g0.w;
            }
        }
        nstep = st + 1.f;
        const float inv = 1.f / (float)cnt;
        const float d1 = 1.f - exp2f(nstep * -0.15200309344504997f);   // 1-0.9^s
        const float d2 = 1.f - exp2f(nstep * -0.0014434169010128458f); // 1-0.999^s
        const float c1  = 0.001f / d1;
        const float id2 = 1.f / d2;

        #define ADAM1(GS, M, P, E, NM, NP, NE)                       \
        {                                                             \
            float g = (GS) * inv;                                     \
            NM = 0.9f * (M) + 0.1f * g;                               \
            NP = 0.999f * (P) + 0.001f * (g * g);                     \
            float stdv = c1 * NM / (sqrtf(NP * id2) + 1e-8f);         \
            NE = (E) - stdv;                                          \
        }
        ADAM1(gs.x, m.x, p.x, e.x, nm.x, np.x, ne.x)
        ADAM1(gs.y, m.y, p.y, e.y, nm.y, np.y, ne.y)
        ADAM1(gs.z, m.z, p.z, e.z, nm.z, np.z, ne.z)
        ADAM1(gs.w, m.w, p.w, e.w, nm.w, np.w, ne.w)
        #undef ADAM1
    } else {
        nstep = st;
        ne = e; nm = m; np = p;
    }

    __stcs(out_emb + i4, ne);
    __stcs(out_mem + i4, nm);
    __stcs(out_pow + i4, np);
    if (lane == 0) out_step[row] = nstep;
}

// ---------------------------------------------------------------------------
extern "C" void kernel_launch(void* const* d_in, const int* in_sizes, int n_in,
                              void* d_out, int out_size) {
    const int*   idx  = (const int*)  d_in[0];
    const float* grad = (const float*)d_in[1];
    const float* emb  = (const float*)d_in[2];
    const float* step = (const float*)d_in[3];
    const float* mem  = (const float*)d_in[4];
    const float* pw   = (const float*)d_in[5];

    const int N = in_sizes[0];
    const int V = in_sizes[3];

    float* out      = (float*)d_out;
    float* out_emb  = out;
    float* out_step = out_emb + (long)V * DD;
    float* out_mem  = out_step + V;
    float* out_pow  = out_mem + (long)V * DD;

    void* counts_ptr = nullptr;
    void* desc_ptr   = nullptr;
    cudaGetSymbolAddress(&counts_ptr, g_counts);
    cudaGetSymbolAddress(&desc_ptr, g_desc);
    cudaMemsetAsync(counts_ptr, 0, (size_t)V * sizeof(int));
    cudaMemsetAsync(desc_ptr, 0, sizeof(unsigned long long) * MAX_SCAN_BLOCKS);

    hist_k<<<592, 256>>>(idx, N);

    const int nb = (V + SCAN_TILE - 1) / SCAN_TILE;
    scan_lb_k<<<nb, SCAN_BS>>>(V);

    scatter_ids_k<<<592, 256>>>(idx, N);

    {
        const long threads = (long)V * 32;
        const int  blocks  = (int)((threads + 255) / 256);
        sadam_update_k<<<blocks, 256>>>((const float4*)grad, (const float4*)emb,
                                        step, (const float4*)mem, (const float4*)pw,
                                        (float4*)out_emb, out_step,
                                        (float4*)out_mem, (float4*)out_pow, V);
    }
}

// round 7
// speedup vs baseline: 1.3137x; 1.2068x over previous
#include <cuda_runtime.h>
#include <cstdint>

// SparseAdam via per-vocab linked lists + single fused streaming pass.
//
// Inputs: 0 idx i32[N], 1 grad f32[N,128], 2 emb f32[V,128], 3 step f32[V],
//         4 mem f32[V,128], 5 pow f32[V,128]
// Output: new_emb[V,128] | new_step[V] | new_mem[V,128] | new_pow[V,128]
//
// 3 graph nodes:
//   memset(head=-1) -> link_k (next[i]=atomicExch(&head[idx[i]],i)) ->
//   update_k (walk list per vocab row; 3.6 GB streaming floor).
// cnt==1 rows (58% of touched) have the chain head->grad: one L2 hop shorter
// than a counting-sort index. cnt is accumulated during the walk.

#define DD 128
#define MAXE (1 << 21)

__device__ int g_head[MAXE];
__device__ int g_next[MAXE];

// ---------------------------------------------------------------------------
// Build linked lists. next[] stores are coalesced (thread owns 4 consecutive i).
// ---------------------------------------------------------------------------
__global__ void link_k(const int* __restrict__ idx, int N) {
    const int n4 = N >> 2;
    const int stride = gridDim.x * blockDim.x;
    const int4* idx4 = (const int4*)idx;
    for (int i = blockIdx.x * blockDim.x + threadIdx.x; i < n4; i += stride) {
        int4 v = __ldg(idx4 + i);
        const int b = i << 2;
        int4 nx;
        nx.x = atomicExch(&g_head[v.x], b);
        nx.y = atomicExch(&g_head[v.y], b + 1);
        nx.z = atomicExch(&g_head[v.z], b + 2);
        nx.w = atomicExch(&g_head[v.w], b + 3);
        ((int4*)g_next)[i] = nx;
    }
    for (int i = (n4 << 2) + blockIdx.x * blockDim.x + threadIdx.x; i < N; i += stride)
        g_next[i] = atomicExch(&g_head[__ldg(idx + i)], i);
}

// ---------------------------------------------------------------------------
// Fused gather + Adam update. One warp per vocab row, float4 per lane.
// Walk the row's linked list; next-pointer and grad loads issue back-to-back.
// ---------------------------------------------------------------------------
__global__ void __launch_bounds__(256, 6)
sadam_update_k(const float4* __restrict__ grad,
               const float4* __restrict__ emb,
               const float*  __restrict__ step_in,
               const float4* __restrict__ mem,
               const float4* __restrict__ pw,
               float4* __restrict__ out_emb,
               float*  __restrict__ out_step,
               float4* __restrict__ out_mem,
               float4* __restrict__ out_pow,
               int V) {
    const long gtid = (long)blockIdx.x * blockDim.x + threadIdx.x;
    const long row  = gtid >> 5;
    if (row >= V) return;
    const int  lane = (int)(gtid & 31);
    const long i4   = row * (DD / 4) + lane;

    int r = __ldg(&g_head[row]);          // -1 if untouched (lane-uniform)
    const float st = __ldg(step_in + row);

    float4 e = __ldcs(emb + i4);
    float4 m = __ldcs(mem + i4);
    float4 p = __ldcs(pw  + i4);

    float4 ne, nm, np;
    float  nstep;

    if (r >= 0) {
        float4 gs = make_float4(0.f, 0.f, 0.f, 0.f);
        int cnt = 0;
        do {
            const int rn = __ldg(&g_next[r]);            // issue with grad load
            float4 g = __ldcs(grad + (long)r * (DD / 4) + lane);
            gs.x += g.x; gs.y += g.y; gs.z += g.z; gs.w += g.w;
            cnt++;
            r = rn;
        } while (r >= 0);

        nstep = st + 1.f;
        const float inv = 1.f / (float)cnt;
        const float d1 = 1.f - exp2f(nstep * -0.15200309344504997f);   // 1-0.9^s
        const float d2 = 1.f - exp2f(nstep * -0.0014434169010128458f); // 1-0.999^s
        const float c1  = 0.001f / d1;
        const float id2 = 1.f / d2;

        #define ADAM1(GS, M, P, E, NM, NP, NE)                       \
        {                                                             \
            float g = (GS) * inv;                                     \
            NM = 0.9f * (M) + 0.1f * g;                               \
            NP = 0.999f * (P) + 0.001f * (g * g);                     \
            float stdv = c1 * NM / (sqrtf(NP * id2) + 1e-8f);         \
            NE = (E) - stdv;                                          \
        }
        ADAM1(gs.x, m.x, p.x, e.x, nm.x, np.x, ne.x)
        ADAM1(gs.y, m.y, p.y, e.y, nm.y, np.y, ne.y)
        ADAM1(gs.z, m.z, p.z, e.z, nm.z, np.z, ne.z)
        ADAM1(gs.w, m.w, p.w, e.w, nm.w, np.w, ne.w)
        #undef ADAM1
    } else {
        nstep = st;
        ne = e; nm = m; np = p;
    }

    __stcs(out_emb + i4, ne);
    __stcs(out_mem + i4, nm);
    __stcs(out_pow + i4, np);
    if (lane == 0) out_step[row] = nstep;
}

// ---------------------------------------------------------------------------
extern "C" void kernel_launch(void* const* d_in, const int* in_sizes, int n_in,
                              void* d_out, int out_size) {
    const int*   idx  = (const int*)  d_in[0];
    const float* grad = (const float*)d_in[1];
    const float* emb  = (const float*)d_in[2];
    const float* step = (const float*)d_in[3];
    const float* mem  = (const float*)d_in[4];
    const float* pw   = (const float*)d_in[5];

    const int N = in_sizes[0];
    const int V = in_sizes[3];

    float* out      = (float*)d_out;
    float* out_emb  = out;
    float* out_step = out_emb + (long)V * DD;
    float* out_mem  = out_step + V;
    float* out_pow  = out_mem + (long)V * DD;

    // head = -1 everywhere (0xFF bytes).
    void* head_ptr = nullptr;
    cudaGetSymbolAddress(&head_ptr, g_head);
    cudaMemsetAsync(head_ptr, 0xFF, (size_t)V * sizeof(int));

    link_k<<<592, 256>>>(idx, N);

    {
        const long threads = (long)V * 32;
        const int  blocks  = (int)((threads + 255) / 256);
        sadam_update_k<<<blocks, 256>>>((const float4*)grad, (const float4*)emb,
                                        step, (const float4*)mem, (const float4*)pw,
                                        (float4*)out_emb, out_step,
                                        (float4*)out_mem, (float4*)out_pow, V);
    }
}